// round 9
// baseline (speedup 1.0000x reference)
#include <cuda_runtime.h>
#include <cuda_fp16.h>
#include <cstdint>
#include <math.h>

#define N_ENTITY 64368
#define N_REL 40
#define DIM 128
#define NUM_BASES 8
#define N_EDGES 1200000
#define BATCH 64
#define MAX_SEED 32

#define SCAN_T 1024
#define SCAN_NBLK 63          // 63*1024 = 64512 >= N_ENTITY

// ---------------- device scratch (static: no allocations allowed) ----------
__device__ __half g_W[(size_t)N_REL * N_ENTITY * DIM];   // 659 MB fp16 projected rows (sparse-written)
__device__ float  g_nodes[(size_t)N_ENTITY * DIM];       // 33 MB
__device__ float  g_u[BATCH * DIM];
__device__ float  g_losspart[BATCH];
__device__ int    g_mask_is_int32;
__device__ unsigned long long g_relmask[N_ENTITY];       // bit r set if (r,src) used
__device__ int    g_cnt[N_ENTITY];
__device__ int    g_off[N_ENTITY + 1];
__device__ int    g_cur[N_ENTITY];
__device__ int    g_blocksum[SCAN_NBLK];
__device__ int    g_eidx[N_EDGES];                       // packed (rel<<17)|src, grouped by dst

// ---------------- seed_mask dtype detection --------------------------------
__global__ void detect_mask_kernel(const unsigned char* mask) {
    __shared__ int s_flag;
    if (threadIdx.x == 0) s_flag = 0;
    __syncthreads();
    for (int i = threadIdx.x; i < BATCH * MAX_SEED; i += blockDim.x) {
        if ((i & 3) != 0 && mask[i] != 0) atomicOr(&s_flag, 1);
    }
    __syncthreads();
    if (threadIdx.x == 0) g_mask_is_int32 = (s_flag == 0) ? 1 : 0;
}

// ---------------- zero relmask + dst counts ---------------------------------
__global__ void zero_aux_kernel() {
    int i = blockIdx.x * blockDim.x + threadIdx.x;
    if (i < N_ENTITY) {
        g_relmask[i] = 0ull;
        g_cnt[i] = 0;
    }
}

// ---------------- build per-src used-relation bitmask + dst histogram -------
__global__ void edge_pass1_kernel(const int* __restrict__ ei, const int* __restrict__ et) {
    int i = blockIdx.x * blockDim.x + threadIdx.x;
    if (i >= N_EDGES) return;
    int src = __ldg(ei + i);
    int dst = __ldg(ei + N_EDGES + i);
    int rel = __ldg(et + i);
    atomicOr(&g_relmask[src], 1ull << rel);
    atomicAdd(&g_cnt[dst], 1);
}

// ---------------- 3-phase exclusive scan of g_cnt -> g_off ------------------
__global__ void scanA_kernel() {
    __shared__ int s[SCAN_T];
    int t = threadIdx.x;
    int idx = blockIdx.x * SCAN_T + t;
    int v = (idx < N_ENTITY) ? g_cnt[idx] : 0;
    s[t] = v;
    __syncthreads();
    for (int o = 1; o < SCAN_T; o <<= 1) {
        int x = (t >= o) ? s[t - o] : 0;
        __syncthreads();
        s[t] += x;
        __syncthreads();
    }
    if (idx < N_ENTITY) g_off[idx] = s[t] - v;     // block-local exclusive
    if (t == SCAN_T - 1) g_blocksum[blockIdx.x] = s[t];
}

__global__ void scanB_kernel() {
    __shared__ int s[SCAN_NBLK];
    int t = threadIdx.x;
    int v = (t < SCAN_NBLK) ? g_blocksum[t] : 0;
    if (t < SCAN_NBLK) s[t] = v;
    __syncthreads();
    for (int o = 1; o < SCAN_NBLK; o <<= 1) {
        int x = (t >= o && t < SCAN_NBLK) ? s[t - o] : 0;
        __syncthreads();
        if (t < SCAN_NBLK) s[t] += x;
        __syncthreads();
    }
    if (t < SCAN_NBLK) g_blocksum[t] = s[t] - v;   // exclusive
}

__global__ void scanC_kernel() {
    int idx = blockIdx.x * SCAN_T + threadIdx.x;
    if (idx < N_ENTITY) {
        int v = g_off[idx] + g_blocksum[blockIdx.x];
        g_off[idx] = v;
        g_cur[idx] = v;
    }
    if (idx == 0) g_off[N_ENTITY] = N_EDGES;
}

__global__ void scatter_kernel(const int* __restrict__ ei, const int* __restrict__ et) {
    int i = blockIdx.x * blockDim.x + threadIdx.x;
    if (i >= N_EDGES) return;
    int src = __ldg(ei + i);
    int dst = __ldg(ei + N_EDGES + i);
    int rel = __ldg(et + i);
    int p = atomicAdd(&g_cur[dst], 1);
    g_eidx[p] = (rel << 17) | src;
}

// ---------------- W[r][n][:] = sum_b att[r,b]*basis[b][n][:] (used r only) --
// warp per node, lane owns 4 dims; only relations present in g_relmask[n].
__global__ void w_kernel(const float* __restrict__ basis, const float* __restrict__ att) {
    __shared__ float s_att[N_REL * NUM_BASES];
    for (int i = threadIdx.x; i < N_REL * NUM_BASES; i += blockDim.x) s_att[i] = att[i];
    __syncthreads();

    int warp = threadIdx.x >> 5;
    int lane = threadIdx.x & 31;
    int n = blockIdx.x * (blockDim.x >> 5) + warp;
    if (n >= N_ENTITY) return;

    unsigned long long m = g_relmask[n];
    if (m == 0ull) return;

    float4 bas[NUM_BASES];
#pragma unroll
    for (int b = 0; b < NUM_BASES; b++)
        bas[b] = *(const float4*)(basis + ((size_t)b * N_ENTITY + n) * DIM + lane * 4);

    while (m) {
        int r = __ffsll((long long)m) - 1;
        m &= m - 1;
        float4 acc = make_float4(0.f, 0.f, 0.f, 0.f);
#pragma unroll
        for (int b = 0; b < NUM_BASES; b++) {
            float c = s_att[r * NUM_BASES + b];
            acc.x += c * bas[b].x;
            acc.y += c * bas[b].y;
            acc.z += c * bas[b].z;
            acc.w += c * bas[b].w;
        }
        __half2 h01 = __floats2half2_rn(acc.x, acc.y);
        __half2 h23 = __floats2half2_rn(acc.z, acc.w);
        uint2 pk = make_uint2(*(unsigned*)&h01, *(unsigned*)&h23);
        ((uint2*)(g_W + ((size_t)r * N_ENTITY + n) * DIM))[lane] = pk;
    }
}

// ---------------- segment aggregation: one warp per dst ---------------------
__device__ __forceinline__ void acc_row(float4& a, int e, int lane) {
    int rel = e >> 17;
    int src = e & 0x1FFFF;
    uint2 pk = __ldg(((const uint2*)g_W) + ((size_t)rel * N_ENTITY + src) * 32 + lane);
    float2 f01 = __half22float2(*(__half2*)&pk.x);
    float2 f23 = __half22float2(*(__half2*)&pk.y);
    a.x += f01.x; a.y += f01.y; a.z += f23.x; a.w += f23.y;
}

__global__ void agg_kernel(const float* __restrict__ root, const float* __restrict__ bias) {
    int dst = blockIdx.x * (blockDim.x >> 5) + (threadIdx.x >> 5);
    if (dst >= N_ENTITY) return;
    int lane = threadIdx.x & 31;

    float4 acc = ((const float4*)root)[(size_t)dst * 32 + lane];
    float4 bb = ((const float4*)bias)[lane];
    acc.x += bb.x; acc.y += bb.y; acc.z += bb.z; acc.w += bb.w;

    int i = __ldg(&g_off[dst]);
    int end = __ldg(&g_off[dst + 1]);

    for (; i + 4 <= end; i += 4) {
        int e0 = __ldg(&g_eidx[i]);
        int e1 = __ldg(&g_eidx[i + 1]);
        int e2 = __ldg(&g_eidx[i + 2]);
        int e3 = __ldg(&g_eidx[i + 3]);
        acc_row(acc, e0, lane);
        acc_row(acc, e1, lane);
        acc_row(acc, e2, lane);
        acc_row(acc, e3, lane);
    }
    for (; i < end; i++) acc_row(acc, __ldg(&g_eidx[i]), lane);

    ((float4*)g_nodes)[(size_t)dst * 32 + lane] = acc;
}

// ---------------- attention pooling over seed sets --------------------------
__global__ void pool_kernel(const int* __restrict__ seed_idx,
                            const void* __restrict__ seed_mask,
                            const float* __restrict__ attn_a,
                            const float* __restrict__ attn_b) {
    int b = blockIdx.x;
    int tid = threadIdx.x;
    int lane = tid & 31;
    int warp = tid >> 5;

    __shared__ float s_h[MAX_SEED][DIM];
    __shared__ float s_e[MAX_SEED];
    __shared__ float s_attn[MAX_SEED];
    __shared__ int   s_idx[MAX_SEED];
    __shared__ unsigned char s_mask[MAX_SEED];

    if (tid < MAX_SEED) {
        s_idx[tid] = seed_idx[b * MAX_SEED + tid];
        int mk;
        if (g_mask_is_int32)
            mk = (((const int*)seed_mask)[b * MAX_SEED + tid] != 0);
        else
            mk = (((const unsigned char*)seed_mask)[b * MAX_SEED + tid] != 0);
        s_mask[tid] = (unsigned char)mk;
    }
    __syncthreads();

    for (int l = 0; l < MAX_SEED; l++)
        s_h[l][tid] = g_nodes[(size_t)s_idx[l] * DIM + tid];
    __syncthreads();

#pragma unroll
    for (int i = 0; i < 8; i++) {
        int l = warp * 8 + i;
        float part = 0.f;
#pragma unroll
        for (int jj = 0; jj < 4; jj++) {
            int j = lane + 32 * jj;
            float m = 0.f;
#pragma unroll 8
            for (int k = 0; k < DIM; k++)
                m += s_h[l][k] * __ldg(attn_a + (size_t)k * DIM + j);
            part += tanhf(m) * __ldg(attn_b + j);
        }
#pragma unroll
        for (int o = 16; o > 0; o >>= 1) part += __shfl_xor_sync(0xffffffffu, part, o);
        if (lane == 0) s_e[l] = part;
    }
    __syncthreads();

    if (warp == 0) {
        float e = s_mask[lane] ? s_e[lane] : -INFINITY;
        float mx = e;
#pragma unroll
        for (int o = 16; o > 0; o >>= 1) mx = fmaxf(mx, __shfl_xor_sync(0xffffffffu, mx, o));
        float p = s_mask[lane] ? __expf(e - mx) : 0.f;
        float sm = p;
#pragma unroll
        for (int o = 16; o > 0; o >>= 1) sm += __shfl_xor_sync(0xffffffffu, sm, o);
        s_attn[lane] = p / sm;
    }
    __syncthreads();

    float u = 0.f;
#pragma unroll
    for (int l = 0; l < MAX_SEED; l++) u += s_attn[l] * s_h[l][tid];
    g_u[b * DIM + tid] = u;
}

// ---------------- scores = u @ nodes^T + output_bias ------------------------
#define TN 64
#define UPAD (BATCH + 4)
#define NPAD (TN + 4)
__global__ void scores_kernel(const float* __restrict__ output_bias,
                              float* __restrict__ out) {
    extern __shared__ float smem[];
    float* s_uT = smem;                    // [DIM][UPAD]
    float* s_nT = smem + DIM * UPAD;       // [DIM][NPAD]

    int tid = threadIdx.x;
    int n0 = blockIdx.x * TN;

    for (int i = tid; i < BATCH * DIM; i += 256) {
        int bb = i >> 7, d = i & 127;
        s_uT[d * UPAD + bb] = g_u[i];
    }
    for (int i = tid; i < TN * DIM; i += 256) {
        int nn = i >> 7, d = i & 127;
        int n = n0 + nn;
        s_nT[d * NPAD + nn] = (n < N_ENTITY) ? g_nodes[(size_t)n * DIM + d] : 0.f;
    }
    __syncthreads();

    int tb = tid >> 4;
    int tn = tid & 15;
    float acc[4][4];
#pragma unroll
    for (int ii = 0; ii < 4; ii++)
#pragma unroll
        for (int jj = 0; jj < 4; jj++) acc[ii][jj] = 0.f;

#pragma unroll 4
    for (int k = 0; k < DIM; k++) {
        float4 ua = *(const float4*)&s_uT[k * UPAD + 4 * tb];
        float4 na = *(const float4*)&s_nT[k * NPAD + 4 * tn];
        float uu[4] = {ua.x, ua.y, ua.z, ua.w};
        float nn[4] = {na.x, na.y, na.z, na.w};
#pragma unroll
        for (int ii = 0; ii < 4; ii++)
#pragma unroll
            for (int jj = 0; jj < 4; jj++)
                acc[ii][jj] += uu[ii] * nn[jj];
    }

#pragma unroll
    for (int ii = 0; ii < 4; ii++) {
        int bb = 4 * tb + ii;
#pragma unroll
        for (int jj = 0; jj < 4; jj++) {
            int n = n0 + 4 * tn + jj;
            if (n < N_ENTITY)
                out[(size_t)bb * N_ENTITY + n] = acc[ii][jj] + output_bias[n];
        }
    }
}

// ---------------- per-row logsumexp + CE ------------------------------------
__global__ void lse_kernel(const float* __restrict__ scores, const int* __restrict__ labels) {
    int b = blockIdx.x;
    int tid = threadIdx.x;
    const float* row = scores + (size_t)b * N_ENTITY;
    __shared__ float s_red[256];

    float mx = -1e30f;
    for (int i = tid; i < N_ENTITY; i += 256) mx = fmaxf(mx, row[i]);
    s_red[tid] = mx;
    __syncthreads();
    for (int o = 128; o > 0; o >>= 1) {
        if (tid < o) s_red[tid] = fmaxf(s_red[tid], s_red[tid + o]);
        __syncthreads();
    }
    float rmax = s_red[0];
    __syncthreads();

    float sum = 0.f;
    for (int i = tid; i < N_ENTITY; i += 256) sum += __expf(row[i] - rmax);
    s_red[tid] = sum;
    __syncthreads();
    for (int o = 128; o > 0; o >>= 1) {
        if (tid < o) s_red[tid] += s_red[tid + o];
        __syncthreads();
    }
    if (tid == 0)
        g_losspart[b] = (logf(s_red[0]) + rmax) - row[labels[b]];
}

__global__ void loss_final_kernel(float* __restrict__ out) {
    __shared__ float s[BATCH];
    int tid = threadIdx.x;
    s[tid] = g_losspart[tid];
    __syncthreads();
    for (int o = 32; o > 0; o >>= 1) {
        if (tid < o) s[tid] += s[tid + o];
        __syncthreads();
    }
    if (tid == 0) out[(size_t)BATCH * N_ENTITY] = s[0] / (float)BATCH;
}

// ---------------- launch ----------------------------------------------------
extern "C" void kernel_launch(void* const* d_in, const int* in_sizes, int n_in,
                              void* d_out, int out_size) {
    const float* basis       = (const float*)d_in[0];
    const float* att         = (const float*)d_in[1];
    const float* root        = (const float*)d_in[2];
    const float* rgcn_bias   = (const float*)d_in[3];
    const float* attn_a      = (const float*)d_in[4];
    const float* attn_b      = (const float*)d_in[5];
    const float* output_bias = (const float*)d_in[6];
    const int*   edge_index  = (const int*)d_in[7];
    const int*   edge_type   = (const int*)d_in[8];
    const int*   seed_idx    = (const int*)d_in[9];
    const void*  seed_mask   = d_in[10];
    const int*   labels      = (const int*)d_in[11];
    float* out = (float*)d_out;

    static cudaStream_t s1 = nullptr;
    static cudaEvent_t ev_pass1 = nullptr, ev_sort = nullptr;
    static int inited = 0;
    if (!inited) {
        cudaFuncSetAttribute(scores_kernel, cudaFuncAttributeMaxDynamicSharedMemorySize,
                             (int)((DIM * UPAD + DIM * NPAD) * sizeof(float)));
        cudaStreamCreateWithFlags(&s1, cudaStreamNonBlocking);
        cudaEventCreateWithFlags(&ev_pass1, cudaEventDisableTiming);
        cudaEventCreateWithFlags(&ev_sort, cudaEventDisableTiming);
        inited = 1;
    }

    detect_mask_kernel<<<1, 256>>>((const unsigned char*)seed_mask);
    zero_aux_kernel<<<(N_ENTITY + 255) / 256, 256>>>();
    edge_pass1_kernel<<<(N_EDGES + 255) / 256, 256>>>(edge_index, edge_type);
    cudaEventRecord(ev_pass1, 0);

    // main stream: long DRAM-bound W precompute
    w_kernel<<<(N_ENTITY + 7) / 8, 256>>>(basis, att);

    // side stream: dst-sort chain, hidden under w_kernel
    cudaStreamWaitEvent(s1, ev_pass1, 0);
    scanA_kernel<<<SCAN_NBLK, SCAN_T, 0, s1>>>();
    scanB_kernel<<<1, 64, 0, s1>>>();
    scanC_kernel<<<SCAN_NBLK, SCAN_T, 0, s1>>>();
    scatter_kernel<<<(N_EDGES + 255) / 256, 256, 0, s1>>>(edge_index, edge_type);
    cudaEventRecord(ev_sort, s1);

    // join: agg needs both W and the sorted edge list
    cudaStreamWaitEvent(0, ev_sort, 0);
    agg_kernel<<<(N_ENTITY + 7) / 8, 256>>>(root, rgcn_bias);       // warp per dst
    pool_kernel<<<BATCH, 128>>>(seed_idx, seed_mask, attn_a, attn_b);
    scores_kernel<<<(N_ENTITY + TN - 1) / TN, 256,
                    (DIM * UPAD + DIM * NPAD) * sizeof(float)>>>(output_bias, out);
    lse_kernel<<<BATCH, 256>>>(out, labels);
    loss_final_kernel<<<1, BATCH>>>(out);
}

// round 10
// speedup vs baseline: 1.3800x; 1.3800x over previous
#include <cuda_runtime.h>
#include <cuda_fp16.h>
#include <cstdint>
#include <math.h>

#define N_ENTITY 64368
#define N_REL 40
#define DIM 128
#define NUM_BASES 8
#define N_EDGES 1200000
#define BATCH 64
#define MAX_SEED 32

#define SCAN_T 1024
#define SCAN_NBLK 63          // 63*1024 = 64512 >= N_ENTITY
#define LSE_SEG 8             // 64368 / 8 = 8046 exactly
#define SEG_LEN (N_ENTITY / LSE_SEG)

// ---------------- device scratch (static: no allocations allowed) ----------
__device__ __half g_W[(size_t)N_REL * N_ENTITY * DIM];   // 659 MB fp16 (sparse-written)
__device__ float  g_nodes[(size_t)N_ENTITY * DIM];       // 33 MB
__device__ float  g_u[BATCH * DIM];
__device__ int    g_mask_is_int32;
__device__ unsigned long long g_relmask[N_ENTITY];       // bit r set if (r,src) used
__device__ int    g_cnt[N_ENTITY];
__device__ int    g_off[N_ENTITY + 1];
__device__ int    g_cur[N_ENTITY];
__device__ int    g_blocksum[SCAN_NBLK];
__device__ int    g_eidx[N_EDGES];                       // packed (rel<<17)|src, grouped by dst
__device__ float  g_pmax[BATCH * LSE_SEG];
__device__ float  g_psum[BATCH * LSE_SEG];

// ---------------- seed_mask dtype detection --------------------------------
__global__ void detect_mask_kernel(const unsigned char* mask) {
    __shared__ int s_flag;
    if (threadIdx.x == 0) s_flag = 0;
    __syncthreads();
    for (int i = threadIdx.x; i < BATCH * MAX_SEED; i += blockDim.x) {
        if ((i & 3) != 0 && mask[i] != 0) atomicOr(&s_flag, 1);
    }
    __syncthreads();
    if (threadIdx.x == 0) g_mask_is_int32 = (s_flag == 0) ? 1 : 0;
}

// ---------------- zero relmask + dst counts ---------------------------------
__global__ void zero_aux_kernel() {
    int i = blockIdx.x * blockDim.x + threadIdx.x;
    if (i < N_ENTITY) {
        g_relmask[i] = 0ull;
        g_cnt[i] = 0;
    }
}

// ---------------- build per-src used-relation bitmask + dst histogram -------
__global__ void edge_pass1_kernel(const int* __restrict__ ei, const int* __restrict__ et) {
    int i = blockIdx.x * blockDim.x + threadIdx.x;
    if (i >= N_EDGES) return;
    int src = __ldg(ei + i);
    int dst = __ldg(ei + N_EDGES + i);
    int rel = __ldg(et + i);
    atomicOr(&g_relmask[src], 1ull << rel);
    atomicAdd(&g_cnt[dst], 1);
}

// ---------------- 3-phase exclusive scan of g_cnt -> g_off ------------------
__global__ void scanA_kernel() {
    __shared__ int s[SCAN_T];
    int t = threadIdx.x;
    int idx = blockIdx.x * SCAN_T + t;
    int v = (idx < N_ENTITY) ? g_cnt[idx] : 0;
    s[t] = v;
    __syncthreads();
    for (int o = 1; o < SCAN_T; o <<= 1) {
        int x = (t >= o) ? s[t - o] : 0;
        __syncthreads();
        s[t] += x;
        __syncthreads();
    }
    if (idx < N_ENTITY) g_off[idx] = s[t] - v;     // block-local exclusive
    if (t == SCAN_T - 1) g_blocksum[blockIdx.x] = s[t];
}

__global__ void scanB_kernel() {
    __shared__ int s[SCAN_NBLK];
    int t = threadIdx.x;
    int v = (t < SCAN_NBLK) ? g_blocksum[t] : 0;
    if (t < SCAN_NBLK) s[t] = v;
    __syncthreads();
    for (int o = 1; o < SCAN_NBLK; o <<= 1) {
        int x = (t >= o && t < SCAN_NBLK) ? s[t - o] : 0;
        __syncthreads();
        if (t < SCAN_NBLK) s[t] += x;
        __syncthreads();
    }
    if (t < SCAN_NBLK) g_blocksum[t] = s[t] - v;   // exclusive
}

__global__ void scanC_kernel() {
    int idx = blockIdx.x * SCAN_T + threadIdx.x;
    if (idx < N_ENTITY) {
        int v = g_off[idx] + g_blocksum[blockIdx.x];
        g_off[idx] = v;
        g_cur[idx] = v;
    }
    if (idx == 0) g_off[N_ENTITY] = N_EDGES;
}

__global__ void scatter_kernel(const int* __restrict__ ei, const int* __restrict__ et) {
    int i = blockIdx.x * blockDim.x + threadIdx.x;
    if (i >= N_EDGES) return;
    int src = __ldg(ei + i);
    int dst = __ldg(ei + N_EDGES + i);
    int rel = __ldg(et + i);
    int p = atomicAdd(&g_cur[dst], 1);
    g_eidx[p] = (rel << 17) | src;
}

// ---------------- W[r][n][:] = sum_b att[r,b]*basis[b][n][:] (used r only) --
// warp per node, lane owns 4 dims. Packed f32x2 FMA (FFMA2) halves FMA issue;
// arithmetic is elementwise fp32 -> bit-identical to scalar FFMA version.
__global__ void w_kernel(const float* __restrict__ basis, const float* __restrict__ att) {
    __shared__ unsigned long long s_att2[N_REL * NUM_BASES];   // (c,c) packed
    for (int i = threadIdx.x; i < N_REL * NUM_BASES; i += blockDim.x) {
        float c = att[i];
        unsigned long long p;
        asm("mov.b64 %0, {%1, %1};" : "=l"(p) : "f"(c));
        s_att2[i] = p;
    }
    __syncthreads();

    int warp = threadIdx.x >> 5;
    int lane = threadIdx.x & 31;
    int n = blockIdx.x * (blockDim.x >> 5) + warp;
    if (n >= N_ENTITY) return;

    unsigned long long m = g_relmask[n];
    if (m == 0ull) return;

    // 8 basis rows, this lane's 4 dims, as packed f32x2 pairs
    unsigned long long bas2[NUM_BASES * 2];
#pragma unroll
    for (int b = 0; b < NUM_BASES; b++) {
        ulonglong2 v = *(const ulonglong2*)(basis + ((size_t)b * N_ENTITY + n) * DIM + lane * 4);
        bas2[2 * b] = v.x;
        bas2[2 * b + 1] = v.y;
    }

    uint2* wp = ((uint2*)g_W) + (size_t)n * (DIM / 4) + lane;   // + r * N_ENTITY*DIM/4

    while (m) {
        int r = __ffsll((long long)m) - 1;
        m &= m - 1;
        unsigned long long a01 = 0ull, a23 = 0ull;
#pragma unroll
        for (int b = 0; b < NUM_BASES; b++) {
            unsigned long long c2 = s_att2[r * NUM_BASES + b];
            asm("fma.rn.f32x2 %0, %1, %2, %0;" : "+l"(a01) : "l"(bas2[2 * b]), "l"(c2));
            asm("fma.rn.f32x2 %0, %1, %2, %0;" : "+l"(a23) : "l"(bas2[2 * b + 1]), "l"(c2));
        }
        float x, y, z, w;
        asm("mov.b64 {%0, %1}, %2;" : "=f"(x), "=f"(y) : "l"(a01));
        asm("mov.b64 {%0, %1}, %2;" : "=f"(z), "=f"(w) : "l"(a23));
        __half2 h01 = __floats2half2_rn(x, y);
        __half2 h23 = __floats2half2_rn(z, w);
        wp[(size_t)r * (N_ENTITY * DIM / 4)] = make_uint2(*(unsigned*)&h01, *(unsigned*)&h23);
    }
}

// ---------------- segment aggregation: one warp per dst ---------------------
__device__ __forceinline__ void acc_row(float4& a, int e, int lane) {
    int rel = e >> 17;
    int src = e & 0x1FFFF;
    uint2 pk = __ldg(((const uint2*)g_W) + ((size_t)rel * N_ENTITY + src) * 32 + lane);
    float2 f01 = __half22float2(*(__half2*)&pk.x);
    float2 f23 = __half22float2(*(__half2*)&pk.y);
    a.x += f01.x; a.y += f01.y; a.z += f23.x; a.w += f23.y;
}

__global__ void agg_kernel(const float* __restrict__ root, const float* __restrict__ bias) {
    int dst = blockIdx.x * (blockDim.x >> 5) + (threadIdx.x >> 5);
    if (dst >= N_ENTITY) return;
    int lane = threadIdx.x & 31;

    float4 acc = ((const float4*)root)[(size_t)dst * 32 + lane];
    float4 bb = ((const float4*)bias)[lane];
    acc.x += bb.x; acc.y += bb.y; acc.z += bb.z; acc.w += bb.w;

    int i = __ldg(&g_off[dst]);
    int end = __ldg(&g_off[dst + 1]);

    for (; i + 4 <= end; i += 4) {
        int e0 = __ldg(&g_eidx[i]);
        int e1 = __ldg(&g_eidx[i + 1]);
        int e2 = __ldg(&g_eidx[i + 2]);
        int e3 = __ldg(&g_eidx[i + 3]);
        acc_row(acc, e0, lane);
        acc_row(acc, e1, lane);
        acc_row(acc, e2, lane);
        acc_row(acc, e3, lane);
    }
    for (; i < end; i++) acc_row(acc, __ldg(&g_eidx[i]), lane);

    ((float4*)g_nodes)[(size_t)dst * 32 + lane] = acc;
}

// ---------------- attention pooling over seed sets --------------------------
__global__ void pool_kernel(const int* __restrict__ seed_idx,
                            const void* __restrict__ seed_mask,
                            const float* __restrict__ attn_a,
                            const float* __restrict__ attn_b) {
    int b = blockIdx.x;
    int tid = threadIdx.x;
    int lane = tid & 31;
    int warp = tid >> 5;

    __shared__ float s_h[MAX_SEED][DIM];
    __shared__ float s_e[MAX_SEED];
    __shared__ float s_attn[MAX_SEED];
    __shared__ int   s_idx[MAX_SEED];
    __shared__ unsigned char s_mask[MAX_SEED];

    if (tid < MAX_SEED) {
        s_idx[tid] = seed_idx[b * MAX_SEED + tid];
        int mk;
        if (g_mask_is_int32)
            mk = (((const int*)seed_mask)[b * MAX_SEED + tid] != 0);
        else
            mk = (((const unsigned char*)seed_mask)[b * MAX_SEED + tid] != 0);
        s_mask[tid] = (unsigned char)mk;
    }
    __syncthreads();

    for (int l = 0; l < MAX_SEED; l++)
        s_h[l][tid] = g_nodes[(size_t)s_idx[l] * DIM + tid];
    __syncthreads();

#pragma unroll
    for (int i = 0; i < 8; i++) {
        int l = warp * 8 + i;
        float part = 0.f;
#pragma unroll
        for (int jj = 0; jj < 4; jj++) {
            int j = lane + 32 * jj;
            float m = 0.f;
#pragma unroll 8
            for (int k = 0; k < DIM; k++)
                m += s_h[l][k] * __ldg(attn_a + (size_t)k * DIM + j);
            part += tanhf(m) * __ldg(attn_b + j);
        }
#pragma unroll
        for (int o = 16; o > 0; o >>= 1) part += __shfl_xor_sync(0xffffffffu, part, o);
        if (lane == 0) s_e[l] = part;
    }
    __syncthreads();

    if (warp == 0) {
        float e = s_mask[lane] ? s_e[lane] : -INFINITY;
        float mx = e;
#pragma unroll
        for (int o = 16; o > 0; o >>= 1) mx = fmaxf(mx, __shfl_xor_sync(0xffffffffu, mx, o));
        float p = s_mask[lane] ? __expf(e - mx) : 0.f;
        float sm = p;
#pragma unroll
        for (int o = 16; o > 0; o >>= 1) sm += __shfl_xor_sync(0xffffffffu, sm, o);
        s_attn[lane] = p / sm;
    }
    __syncthreads();

    float u = 0.f;
#pragma unroll
    for (int l = 0; l < MAX_SEED; l++) u += s_attn[l] * s_h[l][tid];
    g_u[b * DIM + tid] = u;
}

// ---------------- scores = u @ nodes^T + output_bias ------------------------
#define TN 64
#define UPAD (BATCH + 4)
#define NPAD (TN + 4)
__global__ void scores_kernel(const float* __restrict__ output_bias,
                              float* __restrict__ out) {
    extern __shared__ float smem[];
    float* s_uT = smem;                    // [DIM][UPAD]
    float* s_nT = smem + DIM * UPAD;       // [DIM][NPAD]

    int tid = threadIdx.x;
    int n0 = blockIdx.x * TN;

    for (int i = tid; i < BATCH * DIM; i += 256) {
        int bb = i >> 7, d = i & 127;
        s_uT[d * UPAD + bb] = g_u[i];
    }
    for (int i = tid; i < TN * DIM; i += 256) {
        int nn = i >> 7, d = i & 127;
        int n = n0 + nn;
        s_nT[d * NPAD + nn] = (n < N_ENTITY) ? g_nodes[(size_t)n * DIM + d] : 0.f;
    }
    __syncthreads();

    int tb = tid >> 4;
    int tn = tid & 15;
    float acc[4][4];
#pragma unroll
    for (int ii = 0; ii < 4; ii++)
#pragma unroll
        for (int jj = 0; jj < 4; jj++) acc[ii][jj] = 0.f;

#pragma unroll 4
    for (int k = 0; k < DIM; k++) {
        float4 ua = *(const float4*)&s_uT[k * UPAD + 4 * tb];
        float4 na = *(const float4*)&s_nT[k * NPAD + 4 * tn];
        float uu[4] = {ua.x, ua.y, ua.z, ua.w};
        float nn[4] = {na.x, na.y, na.z, na.w};
#pragma unroll
        for (int ii = 0; ii < 4; ii++)
#pragma unroll
            for (int jj = 0; jj < 4; jj++)
                acc[ii][jj] += uu[ii] * nn[jj];
    }

#pragma unroll
    for (int ii = 0; ii < 4; ii++) {
        int bb = 4 * tb + ii;
#pragma unroll
        for (int jj = 0; jj < 4; jj++) {
            int n = n0 + 4 * tn + jj;
            if (n < N_ENTITY)
                out[(size_t)bb * N_ENTITY + n] = acc[ii][jj] + output_bias[n];
        }
    }
}

// ---------------- segmented logsumexp: grid (BATCH, LSE_SEG) ----------------
__global__ void lse_part_kernel(const float* __restrict__ scores) {
    int b = blockIdx.x;
    int s = blockIdx.y;
    int tid = threadIdx.x;
    const float* row = scores + (size_t)b * N_ENTITY + s * SEG_LEN;
    __shared__ float s_red[256];

    float mx = -1e30f;
    for (int i = tid; i < SEG_LEN; i += 256) mx = fmaxf(mx, row[i]);
    s_red[tid] = mx;
    __syncthreads();
    for (int o = 128; o > 0; o >>= 1) {
        if (tid < o) s_red[tid] = fmaxf(s_red[tid], s_red[tid + o]);
        __syncthreads();
    }
    float rmax = s_red[0];
    __syncthreads();

    float sum = 0.f;
    for (int i = tid; i < SEG_LEN; i += 256) sum += __expf(row[i] - rmax);
    s_red[tid] = sum;
    __syncthreads();
    for (int o = 128; o > 0; o >>= 1) {
        if (tid < o) s_red[tid] += s_red[tid + o];
        __syncthreads();
    }
    if (tid == 0) {
        g_pmax[b * LSE_SEG + s] = rmax;
        g_psum[b * LSE_SEG + s] = s_red[0];
    }
}

// merge partials + CE mean; one block of BATCH threads
__global__ void lse_final_kernel(const float* __restrict__ scores,
                                 const int* __restrict__ labels,
                                 float* __restrict__ out) {
    __shared__ float s[BATCH];
    int t = threadIdx.x;   // = batch row
    float M = -1e30f;
#pragma unroll
    for (int j = 0; j < LSE_SEG; j++) M = fmaxf(M, g_pmax[t * LSE_SEG + j]);
    float S = 0.f;
#pragma unroll
    for (int j = 0; j < LSE_SEG; j++)
        S += g_psum[t * LSE_SEG + j] * __expf(g_pmax[t * LSE_SEG + j] - M);
    s[t] = (logf(S) + M) - scores[(size_t)t * N_ENTITY + labels[t]];
    __syncthreads();
    for (int o = 32; o > 0; o >>= 1) {
        if (t < o) s[t] += s[t + o];
        __syncthreads();
    }
    if (t == 0) out[(size_t)BATCH * N_ENTITY] = s[0] / (float)BATCH;
}

// ---------------- launch ----------------------------------------------------
extern "C" void kernel_launch(void* const* d_in, const int* in_sizes, int n_in,
                              void* d_out, int out_size) {
    const float* basis       = (const float*)d_in[0];
    const float* att         = (const float*)d_in[1];
    const float* root        = (const float*)d_in[2];
    const float* rgcn_bias   = (const float*)d_in[3];
    const float* attn_a      = (const float*)d_in[4];
    const float* attn_b      = (const float*)d_in[5];
    const float* output_bias = (const float*)d_in[6];
    const int*   edge_index  = (const int*)d_in[7];
    const int*   edge_type   = (const int*)d_in[8];
    const int*   seed_idx    = (const int*)d_in[9];
    const void*  seed_mask   = d_in[10];
    const int*   labels      = (const int*)d_in[11];
    float* out = (float*)d_out;

    static int smem_set = 0;
    if (!smem_set) {
        cudaFuncSetAttribute(scores_kernel, cudaFuncAttributeMaxDynamicSharedMemorySize,
                             (int)((DIM * UPAD + DIM * NPAD) * sizeof(float)));
        smem_set = 1;
    }

    detect_mask_kernel<<<1, 256>>>((const unsigned char*)seed_mask);
    zero_aux_kernel<<<(N_ENTITY + 255) / 256, 256>>>();
    edge_pass1_kernel<<<(N_EDGES + 255) / 256, 256>>>(edge_index, edge_type);
    scanA_kernel<<<SCAN_NBLK, SCAN_T>>>();
    scanB_kernel<<<1, 64>>>();
    scanC_kernel<<<SCAN_NBLK, SCAN_T>>>();
    scatter_kernel<<<(N_EDGES + 255) / 256, 256>>>(edge_index, edge_type);
    w_kernel<<<(N_ENTITY + 7) / 8, 256>>>(basis, att);              // masked, FFMA2
    agg_kernel<<<(N_ENTITY + 7) / 8, 256>>>(root, rgcn_bias);       // warp per dst
    pool_kernel<<<BATCH, 128>>>(seed_idx, seed_mask, attn_a, attn_b);
    scores_kernel<<<(N_ENTITY + TN - 1) / TN, 256,
                    (DIM * UPAD + DIM * NPAD) * sizeof(float)>>>(output_bias, out);
    lse_part_kernel<<<dim3(BATCH, LSE_SEG), 256>>>(out);
    lse_final_kernel<<<1, BATCH>>>(out, labels, out);
}

// round 11
// speedup vs baseline: 1.3873x; 1.0053x over previous
#include <cuda_runtime.h>
#include <cuda_fp16.h>
#include <cstdint>
#include <math.h>

#define N_ENTITY 64368
#define N_REL 40
#define DIM 128
#define NUM_BASES 8
#define N_EDGES 1200000
#define BATCH 64
#define MAX_SEED 32

#define SCAN_T 1024
#define SCAN_NBLK 63          // 63*1024 = 64512 >= N_ENTITY
#define LSE_SEG 8             // 64368 / 8 = 8046 exactly
#define SEG_LEN (N_ENTITY / LSE_SEG)

// ---------------- device scratch (static: no allocations allowed) ----------
__device__ __half g_W[(size_t)N_REL * N_ENTITY * DIM];   // 659 MB fp16 (sparse-written)
__device__ float  g_nodes[(size_t)N_ENTITY * DIM];       // 33 MB
__device__ float  g_u[BATCH * DIM];
__device__ int    g_mask_is_int32;
__device__ unsigned long long g_relmask[N_ENTITY];       // bit r set if (r,src) used
__device__ int    g_cnt[N_ENTITY];
__device__ int    g_off[N_ENTITY + 1];
__device__ int    g_cur[N_ENTITY];
__device__ int    g_blocksum[SCAN_NBLK];
__device__ int    g_eidx[N_EDGES];                       // packed (rel<<17)|src, grouped by dst
__device__ float  g_pmax[BATCH * LSE_SEG];
__device__ float  g_psum[BATCH * LSE_SEG];

// ---------------- zero relmask + dst counts; last block detects mask dtype --
__global__ void zero_aux_kernel(const unsigned char* mask) {
    if (blockIdx.x == gridDim.x - 1) {
        // seed_mask dtype detection: int32 {0,1} has all bytes at i%4!=0 zero.
        __shared__ int s_flag;
        if (threadIdx.x == 0) s_flag = 0;
        __syncthreads();
        for (int i = threadIdx.x; i < BATCH * MAX_SEED; i += blockDim.x) {
            if ((i & 3) != 0 && mask[i] != 0) atomicOr(&s_flag, 1);
        }
        __syncthreads();
        if (threadIdx.x == 0) g_mask_is_int32 = (s_flag == 0) ? 1 : 0;
        return;
    }
    int i = blockIdx.x * blockDim.x + threadIdx.x;
    if (i < N_ENTITY) {
        g_relmask[i] = 0ull;
        g_cnt[i] = 0;
    }
}

// ---------------- build per-src used-relation bitmask + dst histogram -------
__global__ void edge_pass1_kernel(const int* __restrict__ ei, const int* __restrict__ et) {
    int i = blockIdx.x * blockDim.x + threadIdx.x;
    if (i >= N_EDGES) return;
    int src = __ldg(ei + i);
    int dst = __ldg(ei + N_EDGES + i);
    int rel = __ldg(et + i);
    atomicOr(&g_relmask[src], 1ull << rel);
    atomicAdd(&g_cnt[dst], 1);
}

// ---------------- 2-phase exclusive scan of g_cnt -> g_off ------------------
__global__ void scanA_kernel() {
    __shared__ int s[SCAN_T];
    int t = threadIdx.x;
    int idx = blockIdx.x * SCAN_T + t;
    int v = (idx < N_ENTITY) ? g_cnt[idx] : 0;
    s[t] = v;
    __syncthreads();
    for (int o = 1; o < SCAN_T; o <<= 1) {
        int x = (t >= o) ? s[t - o] : 0;
        __syncthreads();
        s[t] += x;
        __syncthreads();
    }
    if (idx < N_ENTITY) g_off[idx] = s[t] - v;     // block-local exclusive
    if (t == SCAN_T - 1) g_blocksum[blockIdx.x] = s[t];
}

// scanC also re-derives the block-sum prefix locally (drops the scanB launch)
__global__ void scanC_kernel() {
    __shared__ int s[64];
    int t = threadIdx.x;
    if (t < 64) s[t] = (t < SCAN_NBLK) ? g_blocksum[t] : 0;
    __syncthreads();
    for (int o = 1; o < 64; o <<= 1) {
        int x = (t >= o && t < 64) ? s[t - o] : 0;
        __syncthreads();
        if (t < 64) s[t] += x;
        __syncthreads();
    }
    int base = (blockIdx.x == 0) ? 0 : s[blockIdx.x - 1];   // exclusive prefix of this block
    int idx = blockIdx.x * SCAN_T + t;
    if (idx < N_ENTITY) {
        int v = g_off[idx] + base;
        g_off[idx] = v;
        g_cur[idx] = v;
    }
    if (idx == 0) g_off[N_ENTITY] = N_EDGES;
}

__global__ void scatter_kernel(const int* __restrict__ ei, const int* __restrict__ et) {
    int i = blockIdx.x * blockDim.x + threadIdx.x;
    if (i >= N_EDGES) return;
    int src = __ldg(ei + i);
    int dst = __ldg(ei + N_EDGES + i);
    int rel = __ldg(et + i);
    int p = atomicAdd(&g_cur[dst], 1);
    g_eidx[p] = (rel << 17) | src;
}

// ---------------- W[r][n][:] = sum_b att[r,b]*basis[b][n][:] (used r only) --
// warp per node, lane owns 4 dims. Packed f32x2 FMA (FFMA2) halves FMA issue;
// arithmetic is elementwise fp32 -> bit-identical to scalar FFMA version.
__global__ void w_kernel(const float* __restrict__ basis, const float* __restrict__ att) {
    __shared__ unsigned long long s_att2[N_REL * NUM_BASES];   // (c,c) packed
    for (int i = threadIdx.x; i < N_REL * NUM_BASES; i += blockDim.x) {
        float c = att[i];
        unsigned long long p;
        asm("mov.b64 %0, {%1, %1};" : "=l"(p) : "f"(c));
        s_att2[i] = p;
    }
    __syncthreads();

    int warp = threadIdx.x >> 5;
    int lane = threadIdx.x & 31;
    int n = blockIdx.x * (blockDim.x >> 5) + warp;
    if (n >= N_ENTITY) return;

    unsigned long long m = g_relmask[n];
    if (m == 0ull) return;

    unsigned long long bas2[NUM_BASES * 2];
#pragma unroll
    for (int b = 0; b < NUM_BASES; b++) {
        ulonglong2 v = *(const ulonglong2*)(basis + ((size_t)b * N_ENTITY + n) * DIM + lane * 4);
        bas2[2 * b] = v.x;
        bas2[2 * b + 1] = v.y;
    }

    uint2* wp = ((uint2*)g_W) + (size_t)n * (DIM / 4) + lane;   // + r * N_ENTITY*DIM/4

    while (m) {
        int r = __ffsll((long long)m) - 1;
        m &= m - 1;
        unsigned long long a01 = 0ull, a23 = 0ull;
#pragma unroll
        for (int b = 0; b < NUM_BASES; b++) {
            unsigned long long c2 = s_att2[r * NUM_BASES + b];
            asm("fma.rn.f32x2 %0, %1, %2, %0;" : "+l"(a01) : "l"(bas2[2 * b]), "l"(c2));
            asm("fma.rn.f32x2 %0, %1, %2, %0;" : "+l"(a23) : "l"(bas2[2 * b + 1]), "l"(c2));
        }
        float x, y, z, w;
        asm("mov.b64 {%0, %1}, %2;" : "=f"(x), "=f"(y) : "l"(a01));
        asm("mov.b64 {%0, %1}, %2;" : "=f"(z), "=f"(w) : "l"(a23));
        __half2 h01 = __floats2half2_rn(x, y);
        __half2 h23 = __floats2half2_rn(z, w);
        wp[(size_t)r * (N_ENTITY * DIM / 4)] = make_uint2(*(unsigned*)&h01, *(unsigned*)&h23);
    }
}

// ---------------- segment aggregation: one warp per dst ---------------------
__device__ __forceinline__ void acc_row(float4& a, int e, int lane) {
    int rel = e >> 17;
    int src = e & 0x1FFFF;
    uint2 pk = __ldg(((const uint2*)g_W) + ((size_t)rel * N_ENTITY + src) * 32 + lane);
    float2 f01 = __half22float2(*(__half2*)&pk.x);
    float2 f23 = __half22float2(*(__half2*)&pk.y);
    a.x += f01.x; a.y += f01.y; a.z += f23.x; a.w += f23.y;
}

__global__ void agg_kernel(const float* __restrict__ root, const float* __restrict__ bias) {
    int dst = blockIdx.x * (blockDim.x >> 5) + (threadIdx.x >> 5);
    if (dst >= N_ENTITY) return;
    int lane = threadIdx.x & 31;

    float4 acc = ((const float4*)root)[(size_t)dst * 32 + lane];
    float4 bb = ((const float4*)bias)[lane];
    acc.x += bb.x; acc.y += bb.y; acc.z += bb.z; acc.w += bb.w;

    int i = __ldg(&g_off[dst]);
    int end = __ldg(&g_off[dst + 1]);

    // 8-wide software pipeline: 8 independent gathers in flight per lane
    for (; i + 8 <= end; i += 8) {
        int e0 = __ldg(&g_eidx[i]);
        int e1 = __ldg(&g_eidx[i + 1]);
        int e2 = __ldg(&g_eidx[i + 2]);
        int e3 = __ldg(&g_eidx[i + 3]);
        int e4 = __ldg(&g_eidx[i + 4]);
        int e5 = __ldg(&g_eidx[i + 5]);
        int e6 = __ldg(&g_eidx[i + 6]);
        int e7 = __ldg(&g_eidx[i + 7]);
        acc_row(acc, e0, lane);
        acc_row(acc, e1, lane);
        acc_row(acc, e2, lane);
        acc_row(acc, e3, lane);
        acc_row(acc, e4, lane);
        acc_row(acc, e5, lane);
        acc_row(acc, e6, lane);
        acc_row(acc, e7, lane);
    }
    for (; i + 4 <= end; i += 4) {
        int e0 = __ldg(&g_eidx[i]);
        int e1 = __ldg(&g_eidx[i + 1]);
        int e2 = __ldg(&g_eidx[i + 2]);
        int e3 = __ldg(&g_eidx[i + 3]);
        acc_row(acc, e0, lane);
        acc_row(acc, e1, lane);
        acc_row(acc, e2, lane);
        acc_row(acc, e3, lane);
    }
    for (; i < end; i++) acc_row(acc, __ldg(&g_eidx[i]), lane);

    ((float4*)g_nodes)[(size_t)dst * 32 + lane] = acc;
}

// ---------------- attention pooling over seed sets --------------------------
__global__ void pool_kernel(const int* __restrict__ seed_idx,
                            const void* __restrict__ seed_mask,
                            const float* __restrict__ attn_a,
                            const float* __restrict__ attn_b) {
    int b = blockIdx.x;
    int tid = threadIdx.x;
    int lane = tid & 31;
    int warp = tid >> 5;

    __shared__ float s_h[MAX_SEED][DIM];
    __shared__ float s_e[MAX_SEED];
    __shared__ float s_attn[MAX_SEED];
    __shared__ int   s_idx[MAX_SEED];
    __shared__ unsigned char s_mask[MAX_SEED];

    if (tid < MAX_SEED) {
        s_idx[tid] = seed_idx[b * MAX_SEED + tid];
        int mk;
        if (g_mask_is_int32)
            mk = (((const int*)seed_mask)[b * MAX_SEED + tid] != 0);
        else
            mk = (((const unsigned char*)seed_mask)[b * MAX_SEED + tid] != 0);
        s_mask[tid] = (unsigned char)mk;
    }
    __syncthreads();

    for (int l = 0; l < MAX_SEED; l++)
        s_h[l][tid] = g_nodes[(size_t)s_idx[l] * DIM + tid];
    __syncthreads();

#pragma unroll
    for (int i = 0; i < 8; i++) {
        int l = warp * 8 + i;
        float part = 0.f;
#pragma unroll
        for (int jj = 0; jj < 4; jj++) {
            int j = lane + 32 * jj;
            float m = 0.f;
#pragma unroll 8
            for (int k = 0; k < DIM; k++)
                m += s_h[l][k] * __ldg(attn_a + (size_t)k * DIM + j);
            part += tanhf(m) * __ldg(attn_b + j);
        }
#pragma unroll
        for (int o = 16; o > 0; o >>= 1) part += __shfl_xor_sync(0xffffffffu, part, o);
        if (lane == 0) s_e[l] = part;
    }
    __syncthreads();

    if (warp == 0) {
        float e = s_mask[lane] ? s_e[lane] : -INFINITY;
        float mx = e;
#pragma unroll
        for (int o = 16; o > 0; o >>= 1) mx = fmaxf(mx, __shfl_xor_sync(0xffffffffu, mx, o));
        float p = s_mask[lane] ? __expf(e - mx) : 0.f;
        float sm = p;
#pragma unroll
        for (int o = 16; o > 0; o >>= 1) sm += __shfl_xor_sync(0xffffffffu, sm, o);
        s_attn[lane] = p / sm;
    }
    __syncthreads();

    float u = 0.f;
#pragma unroll
    for (int l = 0; l < MAX_SEED; l++) u += s_attn[l] * s_h[l][tid];
    g_u[b * DIM + tid] = u;
}

// ---------------- scores = u @ nodes^T + output_bias ------------------------
#define TN 64
#define UPAD (BATCH + 4)
#define NPAD (TN + 4)
__global__ void scores_kernel(const float* __restrict__ output_bias,
                              float* __restrict__ out) {
    extern __shared__ float smem[];
    float* s_uT = smem;                    // [DIM][UPAD]
    float* s_nT = smem + DIM * UPAD;       // [DIM][NPAD]

    int tid = threadIdx.x;
    int n0 = blockIdx.x * TN;

    for (int i = tid; i < BATCH * DIM; i += 256) {
        int bb = i >> 7, d = i & 127;
        s_uT[d * UPAD + bb] = g_u[i];
    }
    for (int i = tid; i < TN * DIM; i += 256) {
        int nn = i >> 7, d = i & 127;
        int n = n0 + nn;
        s_nT[d * NPAD + nn] = (n < N_ENTITY) ? g_nodes[(size_t)n * DIM + d] : 0.f;
    }
    __syncthreads();

    int tb = tid >> 4;
    int tn = tid & 15;
    float acc[4][4];
#pragma unroll
    for (int ii = 0; ii < 4; ii++)
#pragma unroll
        for (int jj = 0; jj < 4; jj++) acc[ii][jj] = 0.f;

#pragma unroll 4
    for (int k = 0; k < DIM; k++) {
        float4 ua = *(const float4*)&s_uT[k * UPAD + 4 * tb];
        float4 na = *(const float4*)&s_nT[k * NPAD + 4 * tn];
        float uu[4] = {ua.x, ua.y, ua.z, ua.w};
        float nn[4] = {na.x, na.y, na.z, na.w};
#pragma unroll
        for (int ii = 0; ii < 4; ii++)
#pragma unroll
            for (int jj = 0; jj < 4; jj++)
                acc[ii][jj] += uu[ii] * nn[jj];
    }

#pragma unroll
    for (int ii = 0; ii < 4; ii++) {
        int bb = 4 * tb + ii;
#pragma unroll
        for (int jj = 0; jj < 4; jj++) {
            int n = n0 + 4 * tn + jj;
            if (n < N_ENTITY)
                out[(size_t)bb * N_ENTITY + n] = acc[ii][jj] + output_bias[n];
        }
    }
}

// ---------------- segmented logsumexp: grid (BATCH, LSE_SEG) ----------------
__global__ void lse_part_kernel(const float* __restrict__ scores) {
    int b = blockIdx.x;
    int s = blockIdx.y;
    int tid = threadIdx.x;
    const float* row = scores + (size_t)b * N_ENTITY + s * SEG_LEN;
    __shared__ float s_red[256];

    float mx = -1e30f;
    for (int i = tid; i < SEG_LEN; i += 256) mx = fmaxf(mx, row[i]);
    s_red[tid] = mx;
    __syncthreads();
    for (int o = 128; o > 0; o >>= 1) {
        if (tid < o) s_red[tid] = fmaxf(s_red[tid], s_red[tid + o]);
        __syncthreads();
    }
    float rmax = s_red[0];
    __syncthreads();

    float sum = 0.f;
    for (int i = tid; i < SEG_LEN; i += 256) sum += __expf(row[i] - rmax);
    s_red[tid] = sum;
    __syncthreads();
    for (int o = 128; o > 0; o >>= 1) {
        if (tid < o) s_red[tid] += s_red[tid + o];
        __syncthreads();
    }
    if (tid == 0) {
        g_pmax[b * LSE_SEG + s] = rmax;
        g_psum[b * LSE_SEG + s] = s_red[0];
    }
}

// merge partials + CE mean; one block of BATCH threads
__global__ void lse_final_kernel(const float* __restrict__ scores,
                                 const int* __restrict__ labels,
                                 float* __restrict__ out) {
    __shared__ float s[BATCH];
    int t = threadIdx.x;   // = batch row
    float M = -1e30f;
#pragma unroll
    for (int j = 0; j < LSE_SEG; j++) M = fmaxf(M, g_pmax[t * LSE_SEG + j]);
    float S = 0.f;
#pragma unroll
    for (int j = 0; j < LSE_SEG; j++)
        S += g_psum[t * LSE_SEG + j] * __expf(g_pmax[t * LSE_SEG + j] - M);
    s[t] = (logf(S) + M) - scores[(size_t)t * N_ENTITY + labels[t]];
    __syncthreads();
    for (int o = 32; o > 0; o >>= 1) {
        if (t < o) s[t] += s[t + o];
        __syncthreads();
    }
    if (t == 0) out[(size_t)BATCH * N_ENTITY] = s[0] / (float)BATCH;
}

// ---------------- launch ----------------------------------------------------
extern "C" void kernel_launch(void* const* d_in, const int* in_sizes, int n_in,
                              void* d_out, int out_size) {
    const float* basis       = (const float*)d_in[0];
    const float* att         = (const float*)d_in[1];
    const float* root        = (const float*)d_in[2];
    const float* rgcn_bias   = (const float*)d_in[3];
    const float* attn_a      = (const float*)d_in[4];
    const float* attn_b      = (const float*)d_in[5];
    const float* output_bias = (const float*)d_in[6];
    const int*   edge_index  = (const int*)d_in[7];
    const int*   edge_type   = (const int*)d_in[8];
    const int*   seed_idx    = (const int*)d_in[9];
    const void*  seed_mask   = d_in[10];
    const int*   labels      = (const int*)d_in[11];
    float* out = (float*)d_out;

    static int smem_set = 0;
    if (!smem_set) {
        cudaFuncSetAttribute(scores_kernel, cudaFuncAttributeMaxDynamicSharedMemorySize,
                             (int)((DIM * UPAD + DIM * NPAD) * sizeof(float)));
        smem_set = 1;
    }

    zero_aux_kernel<<<(N_ENTITY + 255) / 256 + 1, 256>>>((const unsigned char*)seed_mask);
    edge_pass1_kernel<<<(N_EDGES + 255) / 256, 256>>>(edge_index, edge_type);
    scanA_kernel<<<SCAN_NBLK, SCAN_T>>>();
    scanC_kernel<<<SCAN_NBLK, SCAN_T>>>();
    scatter_kernel<<<(N_EDGES + 255) / 256, 256>>>(edge_index, edge_type);
    w_kernel<<<(N_ENTITY + 7) / 8, 256>>>(basis, att);              // masked, FFMA2
    agg_kernel<<<(N_ENTITY + 7) / 8, 256>>>(root, rgcn_bias);       // warp per dst, 8-wide MLP
    pool_kernel<<<BATCH, 128>>>(seed_idx, seed_mask, attn_a, attn_b);
    scores_kernel<<<(N_ENTITY + TN - 1) / TN, 256,
                    (DIM * UPAD + DIM * NPAD) * sizeof(float)>>>(output_bias, out);
    lse_part_kernel<<<dim3(BATCH, LSE_SEG), 256>>>(out);
    lse_final_kernel<<<1, BATCH>>>(out, labels, out);
}